// round 16
// baseline (speedup 1.0000x reference)
#include <cuda_runtime.h>
#include <math.h>
#include <stdint.h>

// ---------------------------------------------------------------------------
// AutomaticBrightnessAndContrast  (3, H, W) float32 planar — 4-launch version
//
//   k_pass1  : ONE read -> global max + histogram (scale=255 hypothesis).
//              Per-thread private u8 smem counters + DUMMY row for invalid
//              pixels (fully branchless hot loop), packed f32x2 arithmetic,
//              one-sided exact binning (2 cvts/px), per-block partial flush.
//   k_histB  : fallback histogram (scale=1); uniform early-exit when is_norm.
//   k_params : sum partials, cumsum -> alpha/beta; resets d_maxEnc.
//   k_apply  : out = clip(in*alpha_eff + beta_eff, 0, hi)  via __ldcs/__stwt
// ---------------------------------------------------------------------------

#define NBINS 256
#define T_PER_B 256
#define HIST_BLOCKS 456                  // 3/SM on 152 SMs; u8 bound: <=144 incr/thread < 255
#define HIST_ROWS 257                    // 256 bins + dummy row 256 (invalid px)
#define HIST_SMEM (HIST_ROWS * T_PER_B)  // 65,792 B

__device__ unsigned int d_partA[HIST_BLOCKS * NBINS];   // scale=255 hypothesis partials
__device__ unsigned int d_partB[HIST_BLOCKS * NBINS];   // scale=1 hypothesis partials
__device__ unsigned int d_maxEnc = 0u;                  // order-encoded max; params resets
__device__ float d_alpha_eff, d_beta_eff, d_hi;
__device__ int   d_apply;

__device__ __forceinline__ unsigned int enc_f(float f) {
    unsigned int u = __float_as_uint(f);
    return (u & 0x80000000u) ? ~u : (u | 0x80000000u);
}
__device__ __forceinline__ float dec_f(unsigned int e) {
    unsigned int u = (e & 0x80000000u) ? (e & 0x7FFFFFFFu) : ~e;
    return __uint_as_float(u);
}

// ---- packed f32x2 helpers (bitwise-identical per lane to scalar RN ops) ----
__device__ __forceinline__ uint64_t pk2(float f) {
    uint32_t u = __float_as_uint(f);
    return ((uint64_t)u << 32) | (uint64_t)u;
}
__device__ __forceinline__ void mul2(uint64_t& d, uint64_t a, uint64_t b) {
    asm("mul.rn.f32x2 %0, %1, %2;" : "=l"(d) : "l"(a), "l"(b));
}
__device__ __forceinline__ void add2(uint64_t& d, uint64_t a, uint64_t b) {
    asm("add.rn.f32x2 %0, %1, %2;" : "=l"(d) : "l"(a), "l"(b));
}
__device__ __forceinline__ void unpk2f(float& lo, float& hi, uint64_t v) {
    uint32_t a, b;
    asm("mov.b64 {%0,%1}, %2;" : "=r"(a), "=r"(b) : "l"(v));
    lo = __uint_as_float(a); hi = __uint_as_float(b);
}

// bank-conflict-free private column for thread t:
// byte's 4B word index mod 32 == lane -> distinct banks within every warp
__device__ __forceinline__ int col_of(int t) {
    int l = t & 31, w = t >> 5;
    return 4 * l + (w & 3) + ((w >> 2) << 7);
}

// Branchless exact binning + counter update. Reference bin:
// clip(floor(fdiv_rn(g, 255/256)), 0, 255), valid iff g in [0,255].
// c_up = 1 + 32898*2^-23 > 256/255 by ~1.2 ulp => q = RN(g*c_up) >= true
// quotient and <= true bin + 1. One exact compare against the exact-f32
// boundary k*(255/256) restores the exact bin. Invalid pixels go to dummy
// row 256 via SEL (no branch).
__device__ __forceinline__ void px_one(float gy, float qv,
                                       unsigned char* sh, int col) {
    int k = __float2int_rd(qv);
    float bk = __fmul_rn(__int2float_rn(k), 0.99609375f);  // exact b(k)
    k -= (gy < bk) ? 1 : 0;
    k = min(k, 255);
    bool valid = (gy >= 0.0f) && (gy <= 255.0f);
    int bin = valid ? k : NBINS;          // SEL -> dummy row for invalid
    int idx = bin * T_PER_B + col;
    sh[idx] = (unsigned char)(sh[idx] + 1);
}

template <int SCALE_IS_255>
__device__ __forceinline__ void px_pair(uint64_t rp, uint64_t gp, uint64_t bp,
                                        uint64_t C255, uint64_t C299,
                                        uint64_t C587, uint64_t C114,
                                        uint64_t CUP,
                                        unsigned char* sh, int col,
                                        float& lm0, float& lm1) {
    // running max over RAW channel values (register-alias unpack, ~free)
    float r0, r1, g0, g1, b0, b1;
    unpk2f(r0, r1, rp); unpk2f(g0, g1, gp); unpk2f(b0, b1, bp);
    lm0 = fmaxf(lm0, fmaxf(r0, fmaxf(g0, b0)));
    lm1 = fmaxf(lm1, fmaxf(r1, fmaxf(g1, b1)));

    uint64_t ra = rp, ga = gp, ba = bp;
    if (SCALE_IS_255) { mul2(ra, ra, C255); mul2(ga, ga, C255); mul2(ba, ba, C255); }
    uint64_t t0, t1, t2, s, q;
    mul2(t0, ra, C299); mul2(t1, ga, C587); mul2(t2, ba, C114);
    add2(s, t0, t1); add2(s, s, t2);       // ((0.299r + 0.587g) + 0.114b), ref order
    mul2(q, s, CUP);

    float s0, s1, q0, q1;
    unpk2f(s0, s1, s); unpk2f(q0, q1, q);
    px_one(s0, q0, sh, col);
    px_one(s1, q1, sh, col);
}

template <int SCALE_IS_255>
__device__ __forceinline__ void hist_body(const float* __restrict__ img, int npix4,
                                          unsigned int* __restrict__ part_out,
                                          bool do_max) {
    extern __shared__ unsigned char sh8[];
    for (int i = threadIdx.x; i < HIST_SMEM / 4; i += blockDim.x)
        ((unsigned int*)sh8)[i] = 0u;
    __syncthreads();

    const ulonglong2* __restrict__ R = (const ulonglong2*)img;
    const ulonglong2* __restrict__ G = R + npix4;
    const ulonglong2* __restrict__ B = G + npix4;

    const int col = col_of(threadIdx.x);
    const int stride = gridDim.x * blockDim.x;
    int i = blockIdx.x * blockDim.x + threadIdx.x;

    const uint64_t C255 = pk2(255.0f);
    const uint64_t C299 = pk2(0.299f);
    const uint64_t C587 = pk2(0.587f);
    const uint64_t C114 = pk2(0.114f);
    const uint64_t CUP  = pk2(__uint_as_float(0x3F808082u));  // 1+32898*2^-23

    float lm0 = -3.402823466e38f, lm1 = -3.402823466e38f;

    // 2x-unrolled grid-stride main loop (6 LDG.128 in flight per iter, 8 px)
    for (; i + stride < npix4; i += 2 * stride) {
        ulonglong2 rv0 = R[i], gv0 = G[i], bv0 = B[i];
        ulonglong2 rv1 = R[i + stride], gv1 = G[i + stride], bv1 = B[i + stride];
        px_pair<SCALE_IS_255>(rv0.x, gv0.x, bv0.x, C255, C299, C587, C114, CUP, sh8, col, lm0, lm1);
        px_pair<SCALE_IS_255>(rv0.y, gv0.y, bv0.y, C255, C299, C587, C114, CUP, sh8, col, lm0, lm1);
        px_pair<SCALE_IS_255>(rv1.x, gv1.x, bv1.x, C255, C299, C587, C114, CUP, sh8, col, lm0, lm1);
        px_pair<SCALE_IS_255>(rv1.y, gv1.y, bv1.y, C255, C299, C587, C114, CUP, sh8, col, lm0, lm1);
    }
    if (i < npix4) {
        ulonglong2 rv0 = R[i], gv0 = G[i], bv0 = B[i];
        px_pair<SCALE_IS_255>(rv0.x, gv0.x, bv0.x, C255, C299, C587, C114, CUP, sh8, col, lm0, lm1);
        px_pair<SCALE_IS_255>(rv0.y, gv0.y, bv0.y, C255, C299, C587, C114, CUP, sh8, col, lm0, lm1);
    }

    if (do_max) {
        __shared__ float smax[8];
        float lmax = fmaxf(lm0, lm1);
        int lane = threadIdx.x & 31, warp = threadIdx.x >> 5;
        #pragma unroll
        for (int o = 16; o; o >>= 1)
            lmax = fmaxf(lmax, __shfl_xor_sync(0xFFFFFFFFu, lmax, o));
        if (lane == 0) smax[warp] = lmax;
        __syncthreads();
        if (threadIdx.x < 8) {
            float v = smax[threadIdx.x];
            #pragma unroll
            for (int o = 4; o; o >>= 1)
                v = fmaxf(v, __shfl_xor_sync(0xFFu, v, o));
            if (threadIdx.x == 0) atomicMax(&d_maxEnc, enc_f(v));
        }
    }
    __syncthreads();

    // flush: thread t sums bin t's 256 u8 columns via dp4a (skewed uint4 loads),
    // writes this block's partial. Dummy row 256 is never read.
    {
        int t = threadIdx.x;
        const uint4* row = (const uint4*)(sh8 + t * T_PER_B);
        unsigned int s = 0;
        #pragma unroll
        for (int j = 0; j < 16; j++) {
            int k = (j + (t & 15)) & 15;
            uint4 v = row[k];
            s = __dp4a(v.x, 0x01010101u, s);
            s = __dp4a(v.y, 0x01010101u, s);
            s = __dp4a(v.z, 0x01010101u, s);
            s = __dp4a(v.w, 0x01010101u, s);
        }
        part_out[blockIdx.x * NBINS + t] = s;
    }
}

__global__ void __launch_bounds__(T_PER_B, 3)
k_pass1(const float* __restrict__ img, int npix4) {
    hist_body<1>(img, npix4, d_partA, true);
}

__global__ void __launch_bounds__(T_PER_B, 3)
k_histB(const float* __restrict__ img, int npix4) {
    if (dec_f(d_maxEnc) <= 1.0f) return;   // uniform early-exit when normalized
    hist_body<0>(img, npix4, d_partB, false);
}

__global__ void k_params() {
    __shared__ unsigned int sh[NBINS];
    bool is_norm = (dec_f(d_maxEnc) <= 1.0f);
    const unsigned int* __restrict__ part = is_norm ? d_partA : d_partB;

    int t = threadIdx.x;
    unsigned int s = 0;
    #pragma unroll 8
    for (int b = 0; b < HIST_BLOCKS; b++)
        s += part[b * NBINS + t];
    sh[t] = s;
    __syncthreads();

    if (t == 0) {
        long long tot = 0;
        for (int i = 0; i < NBINS; i++) tot += (long long)sh[i];
        float maximum = (float)tot;                       // exact (<= 2^24)
        float clip_value = __fmul_rn(__fdiv_rn(maximum, 100.0f), 0.5f);
        float thresh_hi = __fsub_rn(maximum, clip_value);

        long long acc = 0;
        int min_gray = 0, cnt_hi = 0;
        for (int i = 0; i < NBINS; i++) {
            acc += (long long)sh[i];
            float accf = (float)acc;                      // exact
            if (accf < clip_value) min_gray++;
            if (accf < thresh_hi)  cnt_hi++;
        }
        int max_gray = cnt_hi - 1;

        int sp = max_gray - min_gray; if (sp < 1) sp = 1;
        float alpha = __fdiv_rn(255.0f, (float)sp);
        float beta  = __fmul_rn(-(float)min_gray, alpha);
        float scl   = is_norm ? 255.0f : 1.0f;

        d_alpha_eff = __fdiv_rn(alpha, scl);
        d_beta_eff  = __fdiv_rn(beta,  scl);
        d_hi        = is_norm ? 1.0f : 255.0f;
        d_apply     = (max_gray > min_gray) ? 1 : 0;

        d_maxEnc = 0u;   // self-reset for next graph replay
    }
}

__global__ void __launch_bounds__(256)
k_apply(const float* __restrict__ in, float* __restrict__ out, int n4) {
    const float a  = d_alpha_eff;
    const float b  = d_beta_eff;
    const float hi = d_hi;
    const int   ap = d_apply;

    const float4* __restrict__ I = (const float4*)in;
    float4*       __restrict__ O = (float4*)out;
    const int stride = gridDim.x * blockDim.x;
    int i = blockIdx.x * blockDim.x + threadIdx.x;

    if (ap) {
        for (; i + 3 * stride < n4; i += 4 * stride) {
            float4 v0 = __ldcs(&I[i]);
            float4 v1 = __ldcs(&I[i + stride]);
            float4 v2 = __ldcs(&I[i + 2 * stride]);
            float4 v3 = __ldcs(&I[i + 3 * stride]);
            #define ADJ(v) do {                                                \
                v.x = fminf(fmaxf(fmaf(v.x, a, b), 0.0f), hi);                 \
                v.y = fminf(fmaxf(fmaf(v.y, a, b), 0.0f), hi);                 \
                v.z = fminf(fmaxf(fmaf(v.z, a, b), 0.0f), hi);                 \
                v.w = fminf(fmaxf(fmaf(v.w, a, b), 0.0f), hi);                 \
            } while (0)
            ADJ(v0); ADJ(v1); ADJ(v2); ADJ(v3);
            __stwt(&O[i], v0);
            __stwt(&O[i + stride], v1);
            __stwt(&O[i + 2 * stride], v2);
            __stwt(&O[i + 3 * stride], v3);
        }
        for (; i < n4; i += stride) {
            float4 v = __ldcs(&I[i]);
            ADJ(v);
            #undef ADJ
            __stwt(&O[i], v);
        }
    } else {
        for (; i < n4; i += stride) {
            __stwt(&O[i], __ldcs(&I[i]));
        }
    }
}

extern "C" void kernel_launch(void* const* d_in, const int* in_sizes, int n_in,
                              void* d_out, int out_size) {
    const float* img = (const float*)d_in[0];
    float* out = (float*)d_out;
    int n = in_sizes[0];         // 3*H*W
    int npix4 = (n / 3) / 4;     // 16-byte groups per channel
    int n4 = n / 4;

    // opt-in to 64KB+ dynamic smem (eager host API, capture-legal, no alloc)
    cudaFuncSetAttribute(k_pass1, cudaFuncAttributeMaxDynamicSharedMemorySize, HIST_SMEM);
    cudaFuncSetAttribute(k_histB, cudaFuncAttributeMaxDynamicSharedMemorySize, HIST_SMEM);
    cudaFuncSetAttribute(k_pass1, cudaFuncAttributePreferredSharedMemoryCarveout, 100);
    cudaFuncSetAttribute(k_histB, cudaFuncAttributePreferredSharedMemoryCarveout, 100);

    k_pass1<<<HIST_BLOCKS, T_PER_B, HIST_SMEM>>>(img, npix4);
    k_histB<<<HIST_BLOCKS, T_PER_B, HIST_SMEM>>>(img, npix4);
    k_params<<<1, 256>>>();
    k_apply<<<4864, 256>>>(img, out, n4);
}